// round 11
// baseline (speedup 1.0000x reference)
#include <cuda_runtime.h>

// FourStateQuantizer: elementwise soft quantization over states {-1,-0.5,0.5,1}, T=0.3.
// softmax(-(x-s)^2/T): x^2 cancels -> w_i ∝ exp((2 s_i x - s_i^2)/T). With u = e^{x/T},
// multiply num/den by u^2 -> polynomials in u only:
//   q = [c2(u^4-1) + 0.5 c1 u(u^2-1)] / [c2(u^4+1) + c1 u(u^2+1)]
// Clamp x at +6 (q(6)=1-1.2e-8; keeps u^4 finite); u->0 side safe (q->-1).
// 2 MUFU/elem (EX2 + RCP-divide).
//
// R11: 256-bit global accesses (Blackwell ld/st.global.v8.f32). Same 64 bytes
// per thread as the best R4/R9 shape, but in 2 LDG.256 + 2 STG.256 instead of
// 4+4 128-bit ops: half the LSU/L1tex wavefronts and issue slots per byte.
// Stores keep .cs (write-once stream).

__device__ __forceinline__ float quant1(float x) {
    const float K   = 4.80898346962988f;     // log2(e)/0.3
    const float C1H = 0.2172991042535391f;   // 0.5*exp(-0.25/0.3)
    const float C2  = 0.03567399334725241f;  // exp(-1.0/0.3)
    x = fminf(x, 6.0f);
    float u  = exp2f(x * K);                 // MUFU.EX2
    float u2 = u * u;
    float u4 = u2 * u2;
    float w1 = C1H * u;                      // 0.5*c1*u
    float w2 = w1 + w1;                      // c1*u
    float num = fmaf(w1, u2 - 1.0f, fmaf(C2, u4, -C2));
    float den = fmaf(w2, u2 + 1.0f, fmaf(C2, u4,  C2));
    return __fdividef(num, den);             // MUFU.RCP + FMUL
}

__device__ __forceinline__ void ldg_v8(const float* __restrict__ p, float* r) {
    asm volatile("ld.global.v8.f32 {%0,%1,%2,%3,%4,%5,%6,%7}, [%8];"
                 : "=f"(r[0]), "=f"(r[1]), "=f"(r[2]), "=f"(r[3]),
                   "=f"(r[4]), "=f"(r[5]), "=f"(r[6]), "=f"(r[7])
                 : "l"(p));
}

__device__ __forceinline__ void stg_v8_cs(float* p, const float* r) {
    asm volatile("st.global.cs.v8.f32 [%0], {%1,%2,%3,%4,%5,%6,%7,%8};"
                 :: "l"(p),
                    "f"(r[0]), "f"(r[1]), "f"(r[2]), "f"(r[3]),
                    "f"(r[4]), "f"(r[5]), "f"(r[6]), "f"(r[7])
                 : "memory");
}

#define TPB 256

// Each thread: 16 floats = 2 x v8. Block chunk = 4096 floats.
__global__ __launch_bounds__(TPB) void fourstate_v8_kernel(
    const float* __restrict__ in, float* __restrict__ out)
{
    size_t base = (size_t)blockIdx.x * (TPB * 16) + (size_t)threadIdx.x * 8;
    float x[16], q[16];
    ldg_v8(in + base, x);
    ldg_v8(in + base + TPB * 8, x + 8);
    #pragma unroll
    for (int j = 0; j < 16; j++) q[j] = quant1(x[j]);
    stg_v8_cs(out + base, q);
    stg_v8_cs(out + base + TPB * 8, q + 8);
}

// Fallback/tail kernel (float4 path) for any remainder.
__device__ __forceinline__ float4 quant4(float4 x) {
    float4 q;
    q.x = quant1(x.x); q.y = quant1(x.y);
    q.z = quant1(x.z); q.w = quant1(x.w);
    return q;
}

__global__ void fourstate_tail(const float4* __restrict__ in,
                               float4* __restrict__ out, int start, int n4)
{
    int i = start + blockIdx.x * blockDim.x + threadIdx.x;
    if (i < n4) out[i] = quant4(in[i]);
}

extern "C" void kernel_launch(void* const* d_in, const int* in_sizes, int n_in,
                              void* d_out, int out_size) {
    const float* in = (const float*)d_in[0];
    float* out = (float*)d_out;
    int n = in_sizes[0];                    // 50,331,648
    const int per_block = TPB * 16;         // 4096 floats
    int blocks = n / per_block;             // 12288, exact for this size
    if (blocks > 0)
        fourstate_v8_kernel<<<blocks, TPB>>>(in, out);
    int done = blocks * per_block;
    int rem4 = (n - done) >> 2;             // 0 here; remainder in float4 units
    if (rem4 > 0)
        fourstate_tail<<<(rem4 + 255) / 256, 256>>>(
            (const float4*)in, (float4*)out, done >> 2, (done >> 2) + rem4);
}

// round 12
// speedup vs baseline: 1.0096x; 1.0096x over previous
#include <cuda_runtime.h>

// FourStateQuantizer: elementwise soft quantization over states {-1,-0.5,0.5,1}, T=0.3.
// softmax(-(x-s)^2/T): x^2 cancels -> w_i ∝ exp((2 s_i x - s_i^2)/T). With u = e^{x/T},
// multiply num/den by u^2 -> polynomials in u only:
//   q = [c2(u^4-1) + 0.5 c1 u(u^2-1)] / [c2(u^4+1) + c1 u(u^2+1)]
// Clamp x at +6 (q(6)=1-1.2e-8; keeps u^4 finite); u->0 side safe (q->-1).
// 2 MUFU/elem (EX2 + RCP-divide).
//
// R12: proven R9 body (4 front-batched LDG.128/thread, .cs stores) with
// TPB=512: 6144 CTAs at 4 CTA/SM (64 warps = warp cap at 32 regs -> 100%
// theoretical occ), halved per-CTA launch/index overhead. Final probe of the
// plateau; everything else measured 75-78% DRAM.

__device__ __forceinline__ float quant1(float x) {
    const float K   = 4.80898346962988f;     // log2(e)/0.3
    const float C1H = 0.2172991042535391f;   // 0.5*exp(-0.25/0.3)
    const float C2  = 0.03567399334725241f;  // exp(-1.0/0.3)
    x = fminf(x, 6.0f);
    float u  = exp2f(x * K);                 // MUFU.EX2
    float u2 = u * u;
    float u4 = u2 * u2;
    float w1 = C1H * u;                      // 0.5*c1*u
    float w2 = w1 + w1;                      // c1*u
    float num = fmaf(w1, u2 - 1.0f, fmaf(C2, u4, -C2));
    float den = fmaf(w2, u2 + 1.0f, fmaf(C2, u4,  C2));
    return __fdividef(num, den);             // MUFU.RCP + FMUL
}

__device__ __forceinline__ float4 quant4(float4 x) {
    float4 q;
    q.x = quant1(x.x); q.y = quant1(x.y);
    q.z = quant1(x.z); q.w = quant1(x.w);
    return q;
}

#define TPB    512
#define UNROLL 4

__global__ __launch_bounds__(TPB) void fourstate_kernel(
    const float4* __restrict__ in, float4* __restrict__ out, int n4)
{
    int base = blockIdx.x * (TPB * UNROLL) + threadIdx.x;
    if (base + (UNROLL - 1) * TPB < n4) {
        // fast path (exact for this problem size): 4 front-batched LDG.128
        float4 x0 = in[base];
        float4 x1 = in[base + TPB];
        float4 x2 = in[base + 2 * TPB];
        float4 x3 = in[base + 3 * TPB];
        float4 q0 = quant4(x0);
        float4 q1 = quant4(x1);
        float4 q2 = quant4(x2);
        float4 q3 = quant4(x3);
        __stcs(&out[base],           q0);   // evict-first: output never re-read
        __stcs(&out[base + TPB],     q1);
        __stcs(&out[base + 2 * TPB], q2);
        __stcs(&out[base + 3 * TPB], q3);
    } else {
        #pragma unroll
        for (int j = 0; j < UNROLL; j++) {
            int i = base + j * TPB;
            if (i < n4) __stcs(&out[i], quant4(in[i]));
        }
    }
}

extern "C" void kernel_launch(void* const* d_in, const int* in_sizes, int n_in,
                              void* d_out, int out_size) {
    const float4* in = (const float4*)d_in[0];
    float4* out = (float4*)d_out;
    int n  = in_sizes[0];                 // 50,331,648
    int n4 = n >> 2;                      // 12,582,912 float4s
    int per_block = TPB * UNROLL;         // 2048 float4s per block
    int blocks = (n4 + per_block - 1) / per_block;   // 6144, exact
    fourstate_kernel<<<blocks, TPB>>>(in, out, n4);
}